// round 1
// baseline (speedup 1.0000x reference)
#include <cuda_runtime.h>
#include <cstddef>

#define BB   16
#define SS   4096
#define DIN  512
#define DM   1024
#define NH   16
#define HD   64

// ---------------- scratch (no allocations allowed) ----------------
__device__ float g_x1e[BB * DM];
__device__ float g_q[BB * DM];
__device__ float g_t[BB * NH * DM];          // 1 MB
__device__ float g_u[BB * NH * DIN];         // 0.5 MB
__device__ float g_scores[BB * NH * SS];     // 4 MB (scores -> attn in place)
__device__ float g_ypart[16 * BB * NH * DIN];// 8 MB
__device__ float g_y[BB * NH * DIN];
__device__ float g_ye[BB * NH * DM];
__device__ float g_av[BB * DM];
__device__ float g_part[524288];             // GEMM / proj split-K partials

// ---------------- small projection: out[b][j] = sum_i x[b][i]*W[i][j] (split-K partials)
template <int K, int KS>
__global__ void k_proj(const float* __restrict__ x, const float* __restrict__ W,
                       float* __restrict__ part) {
    constexpr int KC = K / KS;
    int b = blockIdx.x;
    int j = blockIdx.y * 128 + threadIdx.x;
    int ks = blockIdx.z;
    __shared__ float xs[KC];
    for (int i = threadIdx.x; i < KC; i += 128) xs[i] = x[b * K + ks * KC + i];
    __syncthreads();
    float acc = 0.f;
#pragma unroll 8
    for (int i = 0; i < KC; ++i) acc += xs[i] * W[(size_t)(ks * KC + i) * DM + j];
    part[(size_t)ks * (BB * DM) + b * DM + j] = acc;
}

// generic deterministic split reduction (+ optional broadcast bias)
__global__ void k_reduce(const float* __restrict__ part, float* __restrict__ out,
                         const float* __restrict__ bias, int total, int nsplit, int bmod) {
    int i = blockIdx.x * 256 + threadIdx.x;
    if (i >= total) return;
    float s = 0.f;
    for (int z = 0; z < nsplit; ++z) s += part[(size_t)z * total + i];
    if (bias) s += bias[i & (bmod - 1)];
    out[i] = s;
}

// ---------------- t[b,h,j] = sum_d Wk[j, h*64+d] * q[b, h*64+d]
__global__ void k_t(const float* __restrict__ Wk) {
    int h = blockIdx.x;
    int j = blockIdx.y * 128 + threadIdx.x;
    __shared__ float qs[BB * HD];
    for (int l = threadIdx.x; l < BB * HD; l += 128) {
        int b = l >> 6, d = l & 63;
        qs[l] = g_q[b * DM + h * HD + d];
    }
    __syncthreads();
    float acc[BB];
#pragma unroll
    for (int b = 0; b < BB; ++b) acc[b] = 0.f;
    const float* wrow = Wk + (size_t)j * DM + h * HD;
#pragma unroll 4
    for (int d = 0; d < HD; ++d) {
        float w = wrow[d];
#pragma unroll
        for (int b = 0; b < BB; ++b) acc[b] += w * qs[b * HD + d];
    }
#pragma unroll
    for (int b = 0; b < BB; ++b) g_t[(size_t)(b * NH + h) * DM + j] = acc[b];
}

// ---------------- tiled split-K GEMM: C[M,N] = A[M,K] @ B ; B is [N,K] (kmajor) or [K,N]
template <int MM, int NN, int KK, int SPLITS, bool BKMAJOR>
__global__ void k_gemm(const float* __restrict__ A, const float* __restrict__ Bm,
                       float* __restrict__ part) {
    constexpr int KC = KK / SPLITS;
    int n0 = blockIdx.x * 64, m0 = blockIdx.y * 64, k0 = blockIdx.z * KC;
    __shared__ float Asm[16][64];
    __shared__ float Bsm[16][64];
    int tid = threadIdx.x;
    int tx = tid & 15, ty = tid >> 4;
    float acc[4][4] = {};
    for (int kt = 0; kt < KC; kt += 16) {
        {
            int m = tid >> 2, kq = tid & 3;
            float4 a4 = *(const float4*)(A + (size_t)(m0 + m) * KK + k0 + kt + kq * 4);
            Asm[kq * 4 + 0][m] = a4.x; Asm[kq * 4 + 1][m] = a4.y;
            Asm[kq * 4 + 2][m] = a4.z; Asm[kq * 4 + 3][m] = a4.w;
        }
        if constexpr (BKMAJOR) {
            int n = tid >> 2, kq = tid & 3;
            float4 b4 = *(const float4*)(Bm + (size_t)(n0 + n) * KK + k0 + kt + kq * 4);
            Bsm[kq * 4 + 0][n] = b4.x; Bsm[kq * 4 + 1][n] = b4.y;
            Bsm[kq * 4 + 2][n] = b4.z; Bsm[kq * 4 + 3][n] = b4.w;
        } else {
            int kk = tid >> 4, n4 = tid & 15;
            float4 b4 = *(const float4*)(Bm + (size_t)(k0 + kt + kk) * NN + n0 + n4 * 4);
            *(float4*)&Bsm[kk][n4 * 4] = b4;
        }
        __syncthreads();
#pragma unroll
        for (int kk = 0; kk < 16; ++kk) {
            float4 a = *(const float4*)&Asm[kk][ty * 4];
            float4 b = *(const float4*)&Bsm[kk][tx * 4];
            acc[0][0] += a.x * b.x; acc[0][1] += a.x * b.y; acc[0][2] += a.x * b.z; acc[0][3] += a.x * b.w;
            acc[1][0] += a.y * b.x; acc[1][1] += a.y * b.y; acc[1][2] += a.y * b.z; acc[1][3] += a.y * b.w;
            acc[2][0] += a.z * b.x; acc[2][1] += a.z * b.y; acc[2][2] += a.z * b.z; acc[2][3] += a.z * b.w;
            acc[3][0] += a.w * b.x; acc[3][1] += a.w * b.y; acc[3][2] += a.w * b.z; acc[3][3] += a.w * b.w;
        }
        __syncthreads();
    }
    float* p = part + (size_t)blockIdx.z * MM * NN;
#pragma unroll
    for (int i = 0; i < 4; ++i) {
        float4 v = make_float4(acc[i][0], acc[i][1], acc[i][2], acc[i][3]);
        *(float4*)(p + (size_t)(m0 + ty * 4 + i) * NN + n0 + tx * 4) = v;
    }
}

// ---------------- scores: g_scores[b,h,s] = (x2[b,s,:] . g_u[b,h,:]) / 8
__global__ void k_scores(const float* __restrict__ x2) {
    int b = blockIdx.x;
    int s0 = blockIdx.y * 128;
    __shared__ float us[NH * DIN];   // 32 KB
    __shared__ float xs[128][17];    // 8.5 KB, odd-ish stride -> conflict-free row reads
    {
        const float4* src = (const float4*)(g_u + (size_t)b * NH * DIN);
        float4* dst = (float4*)us;
        for (int l = threadIdx.x; l < NH * DIN / 4; l += 128) dst[l] = src[l];
    }
    int r = threadIdx.x;
    float acc[NH];
#pragma unroll
    for (int h = 0; h < NH; ++h) acc[h] = 0.f;
    const float* x2b = x2 + (size_t)b * SS * DIN;
    for (int j0 = 0; j0 < DIN; j0 += 16) {
        __syncthreads();  // (first iter: also publishes us)
#pragma unroll
        for (int v = 0; v < 4; ++v) {
            int l4 = threadIdx.x + v * 128;       // 0..511
            int rr = l4 >> 2, jq = l4 & 3;
            float4 xv = *(const float4*)(x2b + (size_t)(s0 + rr) * DIN + j0 + jq * 4);
            xs[rr][jq * 4 + 0] = xv.x; xs[rr][jq * 4 + 1] = xv.y;
            xs[rr][jq * 4 + 2] = xv.z; xs[rr][jq * 4 + 3] = xv.w;
        }
        __syncthreads();
#pragma unroll
        for (int jj = 0; jj < 16; jj += 4) {
            float x0 = xs[r][jj], x1 = xs[r][jj + 1], x2v = xs[r][jj + 2], x3v = xs[r][jj + 3];
#pragma unroll
            for (int h = 0; h < NH; ++h) {
                float4 u4 = *(const float4*)&us[h * DIN + j0 + jj];  // broadcast
                acc[h] += x0 * u4.x + x1 * u4.y + x2v * u4.z + x3v * u4.w;
            }
        }
    }
#pragma unroll
    for (int h = 0; h < NH; ++h)
        g_scores[((size_t)(b * NH + h) << 12) + s0 + r] = acc[h] * 0.125f;
}

// ---------------- softmax over s (row = b*NH+h), shift-invariant constants dropped upstream
__global__ void k_softmax() {
    int row = blockIdx.x;
    float* sc = g_scores + (size_t)row * SS;
    int tid = threadIdx.x;
    float v[16];
    float mx = -1e30f;
#pragma unroll
    for (int i = 0; i < 16; ++i) { v[i] = sc[tid + i * 256]; mx = fmaxf(mx, v[i]); }
    __shared__ float red[256];
    red[tid] = mx; __syncthreads();
    for (int o = 128; o > 0; o >>= 1) { if (tid < o) red[tid] = fmaxf(red[tid], red[tid + o]); __syncthreads(); }
    mx = red[0]; __syncthreads();
    float sum = 0.f;
#pragma unroll
    for (int i = 0; i < 16; ++i) { v[i] = __expf(v[i] - mx); sum += v[i]; }
    red[tid] = sum; __syncthreads();
    for (int o = 128; o > 0; o >>= 1) { if (tid < o) red[tid] += red[tid + o]; __syncthreads(); }
    float inv = 1.f / red[0];
#pragma unroll
    for (int i = 0; i < 16; ++i) sc[tid + i * 256] = v[i] * inv;
}

// ---------------- weighted sum partials: ypart[c][b,h,:] = sum_{s in chunk c} attn * x3[b,s,:]
__global__ void k_wsum(const float* __restrict__ x3) {
    int b = blockIdx.x, c = blockIdx.y;
    int s0 = c * 256;
    __shared__ float as[NH][256];    // 16 KB
    for (int l = threadIdx.x; l < NH * 256; l += 128) {
        int h = l >> 8, s = l & 255;
        as[h][s] = g_scores[((size_t)(b * NH + h) << 12) + s0 + s];
    }
    __syncthreads();
    float acc[NH * 4];
#pragma unroll
    for (int i = 0; i < NH * 4; ++i) acc[i] = 0.f;
    const float* x3b = x3 + (size_t)b * SS * DIN + threadIdx.x * 4;
    for (int s = 0; s < 256; ++s) {
        float4 xv = *(const float4*)(x3b + (size_t)(s0 + s) * DIN);
#pragma unroll
        for (int h = 0; h < NH; ++h) {
            float w = as[h][s];  // broadcast
            acc[h * 4 + 0] += w * xv.x; acc[h * 4 + 1] += w * xv.y;
            acc[h * 4 + 2] += w * xv.z; acc[h * 4 + 3] += w * xv.w;
        }
    }
    float* yp = g_ypart + (size_t)c * (BB * NH * DIN) + (size_t)(b * NH) * DIN;
#pragma unroll
    for (int h = 0; h < NH; ++h) {
        float4 v = make_float4(acc[h * 4 + 0], acc[h * 4 + 1], acc[h * 4 + 2], acc[h * 4 + 3]);
        *(float4*)(yp + h * DIN + threadIdx.x * 4) = v;
    }
}

// ---------------- av[b, h*64+d] = sum_j ye[b,h,j]*Wv[j, h*64+d] + bv
__global__ void k_av(const float* __restrict__ Wv, const float* __restrict__ bv) {
    int b = blockIdx.x, h = blockIdx.y;
    int d = threadIdx.x & 63, jq = threadIdx.x >> 6;
    __shared__ float yes[DM];
    __shared__ float red[4][64];
    for (int l = threadIdx.x; l < DM; l += 256) yes[l] = g_ye[(size_t)(b * NH + h) * DM + l];
    __syncthreads();
    float acc = 0.f;
    const float* wp = Wv + h * HD + d;
#pragma unroll 8
    for (int j = jq * 256; j < jq * 256 + 256; ++j) acc += yes[j] * wp[(size_t)j * DM];
    red[jq][d] = acc;
    __syncthreads();
    if (jq == 0) {
        float s = red[0][d] + red[1][d] + red[2][d] + red[3][d] + bv[h * HD + d];
        g_av[b * DM + h * HD + d] = s;
    }
}

// ---------------- launch ----------------
extern "C" void kernel_launch(void* const* d_in, const int* in_sizes, int n_in,
                              void* d_out, int out_size) {
    const float* x1  = (const float*)d_in[0];
    const float* x2  = (const float*)d_in[1];
    const float* x3  = (const float*)d_in[2];
    const float* We1 = (const float*)d_in[3];
    const float* be1 = (const float*)d_in[4];
    const float* We2 = (const float*)d_in[5];
    const float* be2 = (const float*)d_in[6];
    const float* Wq  = (const float*)d_in[7];
    const float* bq  = (const float*)d_in[8];
    const float* Wk  = (const float*)d_in[9];
    // d_in[10] = bk: softmax-shift-invariant, exactly dropped
    const float* Wv  = (const float*)d_in[11];
    const float* bv  = (const float*)d_in[12];
    const float* Wo  = (const float*)d_in[13];
    const float* bo  = (const float*)d_in[14];
    float* out = (float*)d_out;

    float *pg_part, *pg_x1e, *pg_q, *pg_t, *pg_u, *pg_ypart, *pg_y, *pg_ye, *pg_av;
    cudaGetSymbolAddress((void**)&pg_part,  g_part);
    cudaGetSymbolAddress((void**)&pg_x1e,   g_x1e);
    cudaGetSymbolAddress((void**)&pg_q,     g_q);
    cudaGetSymbolAddress((void**)&pg_t,     g_t);
    cudaGetSymbolAddress((void**)&pg_u,     g_u);
    cudaGetSymbolAddress((void**)&pg_ypart, g_ypart);
    cudaGetSymbolAddress((void**)&pg_y,     g_y);
    cudaGetSymbolAddress((void**)&pg_ye,    g_ye);
    cudaGetSymbolAddress((void**)&pg_av,    g_av);

    // 1) x1e = x1 @ We1 + be1
    k_proj<512, 4><<<dim3(BB, 8, 4), 128>>>(x1, We1, pg_part);
    k_reduce<<<(BB * DM + 255) / 256, 256>>>(pg_part, pg_x1e, be1, BB * DM, 4, DM);
    // 2) q = x1e @ Wq + bq
    k_proj<1024, 8><<<dim3(BB, 8, 8), 128>>>(pg_x1e, Wq, pg_part);
    k_reduce<<<(BB * DM + 255) / 256, 256>>>(pg_part, pg_q, bq, BB * DM, 8, DM);
    // 3) t[b,h,j] = Wk_h @ q_h
    k_t<<<dim3(NH, 8), 128>>>(Wk);
    // 4) u[b,h,:] = t[b,h,:] @ We2^T   (B is [N=512][K=1024] k-major)
    k_gemm<256, 512, 1024, 4, true><<<dim3(8, 4, 4), 256>>>(pg_t, We2, pg_part);
    k_reduce<<<(256 * 512 + 255) / 256, 256>>>(pg_part, pg_u, nullptr, 256 * 512, 4, DM);
    // 5) scores + softmax
    k_scores<<<dim3(BB, 32), 128>>>(x2);
    k_softmax<<<BB * NH, 256>>>();
    // 6) y[b,h,:] = attn @ x3 (deterministic chunked partials)
    k_wsum<<<dim3(BB, 16), 128>>>(x3);
    k_reduce<<<(256 * 512 + 255) / 256, 256>>>(pg_ypart, pg_y, nullptr, 256 * 512, 16, DM);
    // 7) ye = y @ We2 + be2   (B is [K=512][N=1024] n-major)
    k_gemm<256, 1024, 512, 2, false><<<dim3(16, 4, 2), 256>>>(pg_y, We2, pg_part);
    k_reduce<<<(256 * 1024 + 255) / 256, 256>>>(pg_part, pg_ye, be2, 256 * 1024, 2, DM);
    // 8) av = per-head ye @ Wv_h + bv
    k_av<<<dim3(BB, NH), 256>>>(Wv, bv);
    // 9) out = av @ Wo + bo
    k_proj<1024, 8><<<dim3(BB, 8, 8), 128>>>(pg_av, Wo, pg_part);
    k_reduce<<<(BB * DM + 255) / 256, 256>>>(pg_part, out, bo, BB * DM, 8, DM);
}

// round 3
// speedup vs baseline: 1.1701x; 1.1701x over previous
#include <cuda_runtime.h>
#include <cstddef>

#define BB   16
#define SS   4096
#define DIN  512
#define DM   1024
#define NH   16
#define HD   64

// ---------------- scratch (no allocations allowed) ----------------
__device__ float g_x1e[BB * DM];
__device__ float g_q[BB * DM];
__device__ float g_t[BB * NH * DM];             // 1 MB
__device__ float g_uT[BB * DIN * NH];           // 0.5 MB, [b][i][h]
__device__ float g_scores[BB * NH * SS];        // 4 MB (scores -> attn in place)
__device__ float g_ypart[32 * BB * NH * DIN];   // 16.8 MB, [c][b][h][d]
__device__ float g_y[BB * NH * DIN];
__device__ float g_ye[BB * NH * DM];
__device__ float g_av[BB * DM];
__device__ float g_part[2097152];               // 8 MB split-K partials

// ---------------- f32x2 packed-FMA helpers ----------------
__device__ __forceinline__ unsigned long long pk2(float lo, float hi) {
    unsigned long long r;
    asm("mov.b64 %0, {%1, %2};" : "=l"(r) : "f"(lo), "f"(hi));
    return r;
}
__device__ __forceinline__ unsigned long long ff2(unsigned long long a,
                                                  unsigned long long b,
                                                  unsigned long long c) {
    unsigned long long d;
    asm("fma.rn.f32x2 %0, %1, %2, %3;" : "=l"(d) : "l"(a), "l"(b), "l"(c));
    return d;
}
__device__ __forceinline__ void up2(float& lo, float& hi, unsigned long long a) {
    asm("mov.b64 {%0, %1}, %2;" : "=f"(lo), "=f"(hi) : "l"(a));
}

// ---------------- fused 16-row dense: out[16][1024] = X[16][K] @ W[K][1024] + bias
// grid 32 (j-chunks of 32), block 256 = (32 j-lanes x 8 K-splits)
template <int K>
__global__ void k_dense16(const float* __restrict__ X, const float* __restrict__ W,
                          const float* __restrict__ bias, float* __restrict__ out) {
    __shared__ float xs[256][17];  // [k-slab][b]
    __shared__ float ps[8][512];   // [ks][b*32+jl]
    int tid = threadIdx.x;
    int jl = tid & 31, ks = tid >> 5;
    int j = blockIdx.x * 32 + jl;
    float acc[BB];
#pragma unroll
    for (int b = 0; b < BB; ++b) acc[b] = 0.f;

    for (int k0 = 0; k0 < K; k0 += 256) {
        __syncthreads();
#pragma unroll
        for (int i = 0; i < 16; ++i) {
            int l = tid + i * 256;
            int k = l & 255, b = l >> 8;
            xs[k][b] = X[b * K + k0 + k];
        }
        __syncthreads();
#pragma unroll 8
        for (int kk = ks * 32; kk < ks * 32 + 32; ++kk) {
            float w = W[(size_t)(k0 + kk) * DM + j];
#pragma unroll
            for (int b = 0; b < BB; ++b) acc[b] += w * xs[kk][b];
        }
    }
#pragma unroll
    for (int b = 0; b < BB; ++b) ps[ks][b * 32 + jl] = acc[b];
    __syncthreads();
    for (int o = tid; o < 512; o += 256) {
        int b = o >> 5, jj = o & 31;
        float s = 0.f;
#pragma unroll
        for (int z = 0; z < 8; ++z) s += ps[z][o];
        out[b * DM + blockIdx.x * 32 + jj] = s + bias[blockIdx.x * 32 + jj];
    }
}

// ---------------- t[b,h,j] = sum_d Wk[j, h*64+d] * q[b, h*64+d]
// grid (16 h, 8 j-chunks of 128), block 128 = (32 j-lanes x 4 b-groups)
__global__ void k_t(const float* __restrict__ Wk) {
    int h = blockIdx.x, j0 = blockIdx.y * 128;
    int tid = threadIdx.x;
    int jl = tid & 31, bg = tid >> 5;
    __shared__ float qs[BB][HD];
    __shared__ float wk[32][65];
    for (int l = tid; l < BB * HD; l += 128) {
        int b = l >> 6, d = l & 63;
        qs[b][d] = g_q[b * DM + h * HD + d];
    }
    for (int st = 0; st < 4; ++st) {
        __syncthreads();
#pragma unroll
        for (int i = 0; i < 16; ++i) {
            int l = tid + i * 128;
            int r = l >> 6, d = l & 63;
            wk[r][d] = Wk[(size_t)(j0 + st * 32 + r) * DM + h * HD + d];
        }
        __syncthreads();
        float acc[4] = {0.f, 0.f, 0.f, 0.f};
#pragma unroll 8
        for (int d = 0; d < HD; ++d) {
            float w = wk[jl][d];
#pragma unroll
            for (int bb = 0; bb < 4; ++bb) acc[bb] += w * qs[bg * 4 + bb][d];
        }
        int j = j0 + st * 32 + jl;
#pragma unroll
        for (int bb = 0; bb < 4; ++bb)
            g_t[(size_t)((bg * 4 + bb) * NH + h) * DM + j] = acc[bb];
    }
}

// ---------------- tiled split-K GEMM: C[M,N] = A[M,K] @ B ; B is [N,K] (kmajor) or [K,N]
template <int MM, int NN, int KK, int SPLITS, bool BKMAJOR>
__global__ void k_gemm(const float* __restrict__ A, const float* __restrict__ Bm,
                       float* __restrict__ part) {
    constexpr int KC = KK / SPLITS;
    int n0 = blockIdx.x * 64, m0 = blockIdx.y * 64, k0 = blockIdx.z * KC;
    __shared__ float Asm[16][64];
    __shared__ float Bsm[16][64];
    int tid = threadIdx.x;
    int tx = tid & 15, ty = tid >> 4;
    float acc[4][4] = {};
    for (int kt = 0; kt < KC; kt += 16) {
        {
            int m = tid >> 2, kq = tid & 3;
            float4 a4 = *(const float4*)(A + (size_t)(m0 + m) * KK + k0 + kt + kq * 4);
            Asm[kq * 4 + 0][m] = a4.x; Asm[kq * 4 + 1][m] = a4.y;
            Asm[kq * 4 + 2][m] = a4.z; Asm[kq * 4 + 3][m] = a4.w;
        }
        if constexpr (BKMAJOR) {
            int n = tid >> 2, kq = tid & 3;
            float4 b4 = *(const float4*)(Bm + (size_t)(n0 + n) * KK + k0 + kt + kq * 4);
            Bsm[kq * 4 + 0][n] = b4.x; Bsm[kq * 4 + 1][n] = b4.y;
            Bsm[kq * 4 + 2][n] = b4.z; Bsm[kq * 4 + 3][n] = b4.w;
        } else {
            int kk = tid >> 4, n4 = tid & 15;
            float4 b4 = *(const float4*)(Bm + (size_t)(k0 + kt + kk) * NN + n0 + n4 * 4);
            *(float4*)&Bsm[kk][n4 * 4] = b4;
        }
        __syncthreads();
#pragma unroll
        for (int kk = 0; kk < 16; ++kk) {
            float4 a = *(const float4*)&Asm[kk][ty * 4];
            float4 b = *(const float4*)&Bsm[kk][tx * 4];
            acc[0][0] += a.x * b.x; acc[0][1] += a.x * b.y; acc[0][2] += a.x * b.z; acc[0][3] += a.x * b.w;
            acc[1][0] += a.y * b.x; acc[1][1] += a.y * b.y; acc[1][2] += a.y * b.z; acc[1][3] += a.y * b.w;
            acc[2][0] += a.z * b.x; acc[2][1] += a.z * b.y; acc[2][2] += a.z * b.z; acc[2][3] += a.z * b.w;
            acc[3][0] += a.w * b.x; acc[3][1] += a.w * b.y; acc[3][2] += a.w * b.z; acc[3][3] += a.w * b.w;
        }
        __syncthreads();
    }
    float* p = part + (size_t)blockIdx.z * MM * NN;
#pragma unroll
    for (int i = 0; i < 4; ++i) {
        float4 v = make_float4(acc[i][0], acc[i][1], acc[i][2], acc[i][3]);
        *(float4*)(p + (size_t)(m0 + ty * 4 + i) * NN + n0 + tx * 4) = v;
    }
}

// ---------------- generic deterministic split reduction (+ optional broadcast bias)
template <int NSPLIT>
__global__ void k_reduce(const float* __restrict__ part, float* __restrict__ out,
                         const float* __restrict__ bias, int total, int bmod) {
    int i = blockIdx.x * 256 + threadIdx.x;
    if (i >= total) return;
    float s = 0.f;
#pragma unroll
    for (int z = 0; z < NSPLIT; ++z) s += part[(size_t)z * total + i];
    if (bias) s += bias[i & (bmod - 1)];
    out[i] = s;
}

// ---------------- reduce u partials (8 splits) and write transposed g_uT[b][i][h]
__global__ void k_reduce_ut(const float* __restrict__ part) {
    int e = blockIdx.x * 256 + threadIdx.x;  // 131072 total
    float s = 0.f;
#pragma unroll
    for (int z = 0; z < 8; ++z) s += part[(size_t)z * 131072 + e];
    int m = e >> 9, n = e & 511;
    int b = m >> 4, h = m & 15;
    g_uT[(size_t)(b * DIN + n) * NH + h] = s;
}

// ---------------- scores: g_scores[b,h,s] = (x2[b,s,:] . u[b,h,:]) / 8  (f32x2, h-pairs)
// grid (16 b, 32 s-chunks of 128), block 128 (one s-row per thread)
__global__ void k_scores(const float* __restrict__ x2) {
    int b = blockIdx.x;
    int s0 = blockIdx.y * 128;
    __shared__ float uT[DIN][20];  // [i][h pad] : rows 80 B -> 16B aligned
    __shared__ float xs[128][9];   // [row][j-slab 8 pad]
    int tid = threadIdx.x;
    // stage uT
    for (int l = tid; l < DIN * NH; l += 128) {
        int i = l >> 4, h = l & 15;
        uT[i][h] = g_uT[(size_t)b * DIN * NH + l];
    }
    unsigned long long acc[8];
#pragma unroll
    for (int p = 0; p < 8; ++p) acc[p] = 0ull;
    const float* x2b = x2 + ((size_t)b * SS + s0) * DIN;
    for (int j0 = 0; j0 < DIN; j0 += 8) {
        __syncthreads();  // first iter also publishes uT
#pragma unroll
        for (int v = 0; v < 2; ++v) {
            int f = tid + v * 128;          // float4 index 0..255
            int rr = f >> 1, jq = f & 1;
            float4 xv = *(const float4*)(x2b + (size_t)rr * DIN + j0 + jq * 4);
            xs[rr][jq * 4 + 0] = xv.x; xs[rr][jq * 4 + 1] = xv.y;
            xs[rr][jq * 4 + 2] = xv.z; xs[rr][jq * 4 + 3] = xv.w;
        }
        __syncthreads();
#pragma unroll
        for (int jj = 0; jj < 8; ++jj) {
            float xv = xs[tid][jj];
            unsigned long long xd = pk2(xv, xv);
            const ulonglong2* up = (const ulonglong2*)&uT[j0 + jj][0];
            ulonglong2 u01 = up[0], u23 = up[1];
            acc[0] = ff2(xd, u01.x, acc[0]);
            acc[1] = ff2(xd, u01.y, acc[1]);
            acc[2] = ff2(xd, u23.x, acc[2]);
            acc[3] = ff2(xd, u23.y, acc[3]);
            const ulonglong2* up2p = (const ulonglong2*)&uT[j0 + jj][8];
            ulonglong2 u45 = up2p[0], u67 = up2p[1];
            acc[4] = ff2(xd, u45.x, acc[4]);
            acc[5] = ff2(xd, u45.y, acc[5]);
            acc[6] = ff2(xd, u67.x, acc[6]);
            acc[7] = ff2(xd, u67.y, acc[7]);
        }
    }
#pragma unroll
    for (int p = 0; p < 8; ++p) {
        float lo, hi;
        up2(lo, hi, acc[p]);
        g_scores[((size_t)(b * NH + 2 * p) << 12) + s0 + tid]     = lo * 0.125f;
        g_scores[((size_t)(b * NH + 2 * p + 1) << 12) + s0 + tid] = hi * 0.125f;
    }
}

// ---------------- softmax over s (row = b*NH+h)
__global__ void k_softmax() {
    int row = blockIdx.x;
    float* sc = g_scores + (size_t)row * SS;
    int tid = threadIdx.x;
    float v[16];
    float mx = -1e30f;
#pragma unroll
    for (int i = 0; i < 16; ++i) { v[i] = sc[tid + i * 256]; mx = fmaxf(mx, v[i]); }
    __shared__ float red[256];
    red[tid] = mx; __syncthreads();
    for (int o = 128; o > 0; o >>= 1) { if (tid < o) red[tid] = fmaxf(red[tid], red[tid + o]); __syncthreads(); }
    mx = red[0]; __syncthreads();
    float sum = 0.f;
#pragma unroll
    for (int i = 0; i < 16; ++i) { v[i] = __expf(v[i] - mx); sum += v[i]; }
    red[tid] = sum; __syncthreads();
    for (int o = 128; o > 0; o >>= 1) { if (tid < o) red[tid] += red[tid + o]; __syncthreads(); }
    float inv = 1.f / red[0];
#pragma unroll
    for (int i = 0; i < 16; ++i) sc[tid + i * 256] = v[i] * inv;
}

// ---------------- weighted-sum partials (f32x2, h-pairs): ypart[c][b][h][d]
// grid (16 b, 32 s-chunks of 128), block 128 (4 d per thread)
__global__ void k_wsum(const float* __restrict__ x3) {
    int b = blockIdx.x, c = blockIdx.y;
    int s0 = c * 128;
    __shared__ float at[128][20];  // [s][h pad] rows 80B -> 16B aligned
    int tid = threadIdx.x;
    for (int l = tid; l < NH * 128; l += 128) {
        int h = l >> 7, s = l & 127;
        at[s][h] = g_scores[((size_t)(b * NH + h) << 12) + s0 + s];
    }
    __syncthreads();
    unsigned long long acc[8][4];  // [h-pair][d]
#pragma unroll
    for (int p = 0; p < 8; ++p)
#pragma unroll
        for (int d = 0; d < 4; ++d) acc[p][d] = 0ull;
    int d0 = tid * 4;
    const float* x3b = x3 + ((size_t)b * SS + s0) * DIN + d0;
#pragma unroll 4
    for (int s = 0; s < 128; ++s) {
        float4 xv = *(const float4*)(x3b + (size_t)s * DIN);
        unsigned long long xd[4];
        xd[0] = pk2(xv.x, xv.x); xd[1] = pk2(xv.y, xv.y);
        xd[2] = pk2(xv.z, xv.z); xd[3] = pk2(xv.w, xv.w);
        const ulonglong2* wp = (const ulonglong2*)&at[s][0];
        ulonglong2 wA = wp[0], wB = wp[1], wC = wp[2], wD = wp[3];
        unsigned long long w[8] = {wA.x, wA.y, wB.x, wB.y, wC.x, wC.y, wD.x, wD.y};
#pragma unroll
        for (int p = 0; p < 8; ++p) {
#pragma unroll
            for (int d = 0; d < 4; ++d) acc[p][d] = ff2(xd[d], w[p], acc[p][d]);
        }
    }
    float* yp = g_ypart + ((size_t)(c * BB + b) * NH) * DIN;
#pragma unroll
    for (int p = 0; p < 8; ++p) {
        float lo[4], hi[4];
#pragma unroll
        for (int d = 0; d < 4; ++d) up2(lo[d], hi[d], acc[p][d]);
        *(float4*)(yp + (2 * p) * DIN + d0)     = make_float4(lo[0], lo[1], lo[2], lo[3]);
        *(float4*)(yp + (2 * p + 1) * DIN + d0) = make_float4(hi[0], hi[1], hi[2], hi[3]);
    }
}

// ---------------- av[b, h*64+d] = sum_j ye[b,h,j]*Wv[j, h*64+d] + bv
__global__ void k_av(const float* __restrict__ Wv, const float* __restrict__ bv) {
    int b = blockIdx.x, h = blockIdx.y;
    int d = threadIdx.x & 63, jq = threadIdx.x >> 6;
    __shared__ float yes[DM];
    __shared__ float red[4][64];
    for (int l = threadIdx.x; l < DM; l += 256) yes[l] = g_ye[(size_t)(b * NH + h) * DM + l];
    __syncthreads();
    float acc = 0.f;
    const float* wp = Wv + h * HD + d;
#pragma unroll 8
    for (int j = jq * 256; j < jq * 256 + 256; ++j) acc += yes[j] * wp[(size_t)j * DM];
    red[jq][d] = acc;
    __syncthreads();
    if (jq == 0) {
        float s = red[0][d] + red[1][d] + red[2][d] + red[3][d] + bv[h * HD + d];
        g_av[b * DM + h * HD + d] = s;
    }
}

// ---------------- launch ----------------
extern "C" void kernel_launch(void* const* d_in, const int* in_sizes, int n_in,
                              void* d_out, int out_size) {
    const float* x1  = (const float*)d_in[0];
    const float* x2  = (const float*)d_in[1];
    const float* x3  = (const float*)d_in[2];
    const float* We1 = (const float*)d_in[3];
    const float* be1 = (const float*)d_in[4];
    const float* We2 = (const float*)d_in[5];
    const float* be2 = (const float*)d_in[6];
    const float* Wq  = (const float*)d_in[7];
    const float* bq  = (const float*)d_in[8];
    const float* Wk  = (const float*)d_in[9];
    // d_in[10] = bk: softmax-shift-invariant, exactly dropped
    const float* Wv  = (const float*)d_in[11];
    const float* bv  = (const float*)d_in[12];
    const float* Wo  = (const float*)d_in[13];
    const float* bo  = (const float*)d_in[14];
    float* out = (float*)d_out;

    float *pg_part, *pg_x1e, *pg_q, *pg_t, *pg_ypart, *pg_y, *pg_ye, *pg_av;
    cudaGetSymbolAddress((void**)&pg_part,  g_part);
    cudaGetSymbolAddress((void**)&pg_x1e,   g_x1e);
    cudaGetSymbolAddress((void**)&pg_q,     g_q);
    cudaGetSymbolAddress((void**)&pg_t,     g_t);
    cudaGetSymbolAddress((void**)&pg_ypart, g_ypart);
    cudaGetSymbolAddress((void**)&pg_y,     g_y);
    cudaGetSymbolAddress((void**)&pg_ye,    g_ye);
    cudaGetSymbolAddress((void**)&pg_av,    g_av);

    // 1) x1e = x1 @ We1 + be1         (one fused launch)
    k_dense16<512><<<32, 256>>>(x1, We1, be1, pg_x1e);
    // 2) q = x1e @ Wq + bq            (one fused launch)
    k_dense16<1024><<<32, 256>>>(pg_x1e, Wq, bq, pg_q);
    // 3) t[b,h,j] = Wk_h @ q_h
    k_t<<<dim3(NH, 8), 128>>>(Wk);
    // 4) u[b,h,:] = t[b,h,:] @ We2^T  -> transposed g_uT
    k_gemm<256, 512, 1024, 8, true><<<dim3(8, 4, 8), 256>>>(pg_t, We2, pg_part);
    k_reduce_ut<<<512, 256>>>(pg_part);
    // 5) scores + softmax
    k_scores<<<dim3(BB, 32), 128>>>(x2);
    k_softmax<<<BB * NH, 256>>>();
    // 6) y[b,h,:] = attn @ x3
    k_wsum<<<dim3(BB, 32), 128>>>(x3);
    k_reduce<32><<<512, 256>>>(pg_ypart, pg_y, nullptr, 131072, DM);
    // 7) ye = y @ We2 + be2
    k_gemm<256, 1024, 512, 4, false><<<dim3(16, 4, 4), 256>>>(pg_y, We2, pg_part);
    k_reduce<4><<<1024, 256>>>(pg_part, pg_ye, be2, 262144, DM);
    // 8) av = per-head ye @ Wv_h + bv
    k_av<<<dim3(BB, NH), 256>>>(Wv, bv);
    // 9) out = av @ Wo + bo           (one fused launch)
    k_dense16<1024><<<32, 256>>>(pg_av, Wo, bo, out);
}

// round 4
// speedup vs baseline: 1.4377x; 1.2287x over previous
#include <cuda_runtime.h>
#include <cstddef>

#define BB   16
#define SS   4096
#define DIN  512
#define DM   1024
#define NH   16
#define HD   64

// ---------------- scratch (no allocations allowed) ----------------
__device__ float g_x1e[BB * DM];
__device__ float g_q[BB * DM];
__device__ float g_t[BB * NH * DM];             // 1 MB
__device__ float g_uT[BB * DIN * NH];           // 0.5 MB, [b][i][h]
__device__ float g_scores[BB * NH * SS];        // 4 MB (scores -> attn in place)
__device__ float g_ypart[32 * BB * NH * DIN];   // 16.8 MB, [c][b][h][d]
__device__ float g_y[BB * NH * DIN];
__device__ float g_ye[BB * NH * DM];
__device__ float g_av[BB * DM];
__device__ float g_part[2097152];               // 8 MB split-K partials

// ---------------- f32x2 packed-FMA helpers ----------------
__device__ __forceinline__ unsigned long long pk2(float lo, float hi) {
    unsigned long long r;
    asm("mov.b64 %0, {%1, %2};" : "=l"(r) : "f"(lo), "f"(hi));
    return r;
}
__device__ __forceinline__ unsigned long long ff2(unsigned long long a,
                                                  unsigned long long b,
                                                  unsigned long long c) {
    unsigned long long d;
    asm("fma.rn.f32x2 %0, %1, %2, %3;" : "=l"(d) : "l"(a), "l"(b), "l"(c));
    return d;
}
__device__ __forceinline__ void up2(float& lo, float& hi, unsigned long long a) {
    asm("mov.b64 {%0, %1}, %2;" : "=f"(lo), "=f"(hi) : "l"(a));
}

// ---------------- fused 16-row dense: out[16][1024] = X[16][K] @ W[K][1024] + bias
// grid 64 (j-chunks of 16), block 256 = (16 j-lanes x 16 K-splits)
template <int K>
__global__ void k_dense16(const float* __restrict__ X, const float* __restrict__ W,
                          const float* __restrict__ bias, float* __restrict__ out) {
    __shared__ float xs[256][17];  // [k-slab][b]
    __shared__ float ps[16][256];  // [ks][b*16+jl]
    int tid = threadIdx.x;
    int jl = tid & 15, ks = tid >> 4;
    int j = blockIdx.x * 16 + jl;
    float acc[BB];
#pragma unroll
    for (int b = 0; b < BB; ++b) acc[b] = 0.f;

    for (int k0 = 0; k0 < K; k0 += 256) {
        __syncthreads();
#pragma unroll
        for (int i = 0; i < 16; ++i) {
            int l = tid + i * 256;
            int k = l & 255, b = l >> 8;
            xs[k][b] = X[b * K + k0 + k];
        }
        __syncthreads();
#pragma unroll 8
        for (int kk = ks * 16; kk < ks * 16 + 16; ++kk) {
            float w = W[(size_t)(k0 + kk) * DM + j];
#pragma unroll
            for (int b = 0; b < BB; ++b) acc[b] += w * xs[kk][b];
        }
    }
#pragma unroll
    for (int b = 0; b < BB; ++b) ps[ks][b * 16 + jl] = acc[b];
    __syncthreads();
    {
        int o = tid;                  // 0..255 = (b, jl)
        int b = o >> 4, jj = o & 15;
        float s = 0.f;
#pragma unroll
        for (int z = 0; z < 16; ++z) s += ps[z][o];
        out[b * DM + blockIdx.x * 16 + jj] = s + bias[blockIdx.x * 16 + jj];
    }
}

// ---------------- t[b,h,j] = sum_d Wk[j, h*64+d] * q[b, h*64+d]
// grid (16 h, 8 j-chunks of 128), block 128 = (32 j-lanes x 4 b-groups)
__global__ void k_t(const float* __restrict__ Wk) {
    int h = blockIdx.x, j0 = blockIdx.y * 128;
    int tid = threadIdx.x;
    int jl = tid & 31, bg = tid >> 5;
    __shared__ float qs[BB][HD];
    __shared__ float wk[32][65];
    for (int l = tid; l < BB * HD; l += 128) {
        int b = l >> 6, d = l & 63;
        qs[b][d] = g_q[b * DM + h * HD + d];
    }
    for (int st = 0; st < 4; ++st) {
        __syncthreads();
#pragma unroll
        for (int i = 0; i < 16; ++i) {
            int l = tid + i * 128;
            int r = l >> 6, d = l & 63;
            wk[r][d] = Wk[(size_t)(j0 + st * 32 + r) * DM + h * HD + d];
        }
        __syncthreads();
        float acc[4] = {0.f, 0.f, 0.f, 0.f};
#pragma unroll 8
        for (int d = 0; d < HD; ++d) {
            float w = wk[jl][d];
#pragma unroll
            for (int bb = 0; bb < 4; ++bb) acc[bb] += w * qs[bg * 4 + bb][d];
        }
        int j = j0 + st * 32 + jl;
#pragma unroll
        for (int bb = 0; bb < 4; ++bb)
            g_t[(size_t)((bg * 4 + bb) * NH + h) * DM + j] = acc[bb];
    }
}

// ---------------- tiled split-K GEMM: C[M,N] = A[M,K] @ B ; B is [N,K] (kmajor) or [K,N]
template <int MM, int NN, int KK, int SPLITS, bool BKMAJOR>
__global__ void k_gemm(const float* __restrict__ A, const float* __restrict__ Bm,
                       float* __restrict__ part) {
    constexpr int KC = KK / SPLITS;
    int n0 = blockIdx.x * 64, m0 = blockIdx.y * 64, k0 = blockIdx.z * KC;
    __shared__ float Asm[16][64];
    __shared__ float Bsm[16][64];
    int tid = threadIdx.x;
    int tx = tid & 15, ty = tid >> 4;
    float acc[4][4] = {};
    for (int kt = 0; kt < KC; kt += 16) {
        {
            int m = tid >> 2, kq = tid & 3;
            float4 a4 = *(const float4*)(A + (size_t)(m0 + m) * KK + k0 + kt + kq * 4);
            Asm[kq * 4 + 0][m] = a4.x; Asm[kq * 4 + 1][m] = a4.y;
            Asm[kq * 4 + 2][m] = a4.z; Asm[kq * 4 + 3][m] = a4.w;
        }
        if constexpr (BKMAJOR) {
            int n = tid >> 2, kq = tid & 3;
            float4 b4 = *(const float4*)(Bm + (size_t)(n0 + n) * KK + k0 + kt + kq * 4);
            Bsm[kq * 4 + 0][n] = b4.x; Bsm[kq * 4 + 1][n] = b4.y;
            Bsm[kq * 4 + 2][n] = b4.z; Bsm[kq * 4 + 3][n] = b4.w;
        } else {
            int kk = tid >> 4, n4 = tid & 15;
            float4 b4 = *(const float4*)(Bm + (size_t)(k0 + kt + kk) * NN + n0 + n4 * 4);
            *(float4*)&Bsm[kk][n4 * 4] = b4;
        }
        __syncthreads();
#pragma unroll
        for (int kk = 0; kk < 16; ++kk) {
            float4 a = *(const float4*)&Asm[kk][ty * 4];
            float4 b = *(const float4*)&Bsm[kk][tx * 4];
            acc[0][0] += a.x * b.x; acc[0][1] += a.x * b.y; acc[0][2] += a.x * b.z; acc[0][3] += a.x * b.w;
            acc[1][0] += a.y * b.x; acc[1][1] += a.y * b.y; acc[1][2] += a.y * b.z; acc[1][3] += a.y * b.w;
            acc[2][0] += a.z * b.x; acc[2][1] += a.z * b.y; acc[2][2] += a.z * b.z; acc[2][3] += a.z * b.w;
            acc[3][0] += a.w * b.x; acc[3][1] += a.w * b.y; acc[3][2] += a.w * b.z; acc[3][3] += a.w * b.w;
        }
        __syncthreads();
    }
    float* p = part + (size_t)blockIdx.z * MM * NN;
#pragma unroll
    for (int i = 0; i < 4; ++i) {
        float4 v = make_float4(acc[i][0], acc[i][1], acc[i][2], acc[i][3]);
        *(float4*)(p + (size_t)(m0 + ty * 4 + i) * NN + n0 + tx * 4) = v;
    }
}

// ---------------- generic deterministic split reduction (+ optional broadcast bias)
template <int NSPLIT>
__global__ void k_reduce(const float* __restrict__ part, float* __restrict__ out,
                         const float* __restrict__ bias, int total, int bmod) {
    int i = blockIdx.x * 256 + threadIdx.x;
    if (i >= total) return;
    float s = 0.f;
#pragma unroll
    for (int z = 0; z < NSPLIT; ++z) s += part[(size_t)z * total + i];
    if (bias) s += bias[i & (bmod - 1)];
    out[i] = s;
}

// ---------------- reduce u partials (16 splits) and write transposed g_uT[b][i][h]
__global__ void k_reduce_ut(const float* __restrict__ part) {
    int e = blockIdx.x * 256 + threadIdx.x;  // 131072 total
    float s = 0.f;
#pragma unroll
    for (int z = 0; z < 16; ++z) s += part[(size_t)z * 131072 + e];
    int m = e >> 9, n = e & 511;
    int b = m >> 4, h = m & 15;
    g_uT[(size_t)(b * DIN + n) * NH + h] = s;
}

// ---------------- scores: g_scores[b,h,s] = (x2[b,s,:] . u[b,h,:]) / 8  (f32x2, h-pairs)
// grid (16 b, 32 s-chunks of 128), block 128 (one s-row per thread); j-slab 16
__global__ void k_scores(const float* __restrict__ x2) {
    int b = blockIdx.x;
    int s0 = blockIdx.y * 128;
    __shared__ float uT[DIN][16];  // 32 KB; inner reads are same-address broadcasts
    __shared__ float xs[128][17];  // 8.7 KB; read stride 17 -> conflict-free
    int tid = threadIdx.x;
    for (int l = tid; l < DIN * NH; l += 128) {
        uT[l >> 4][l & 15] = g_uT[(size_t)b * DIN * NH + l];
    }
    unsigned long long acc[8];
#pragma unroll
    for (int p = 0; p < 8; ++p) acc[p] = 0ull;
    const float* x2b = x2 + ((size_t)b * SS + s0) * DIN;
    for (int j0 = 0; j0 < DIN; j0 += 16) {
        __syncthreads();  // first iter also publishes uT
#pragma unroll
        for (int v = 0; v < 4; ++v) {
            int f = tid + v * 128;          // float4 index 0..511
            int rr = f >> 2, jq = f & 3;
            float4 xv = *(const float4*)(x2b + (size_t)rr * DIN + j0 + jq * 4);
            xs[rr][jq * 4 + 0] = xv.x; xs[rr][jq * 4 + 1] = xv.y;
            xs[rr][jq * 4 + 2] = xv.z; xs[rr][jq * 4 + 3] = xv.w;
        }
        __syncthreads();
#pragma unroll
        for (int jj = 0; jj < 16; ++jj) {
            float xv = xs[tid][jj];
            unsigned long long xd = pk2(xv, xv);
            const ulonglong2* up = (const ulonglong2*)&uT[j0 + jj][0];
            ulonglong2 u01 = up[0], u23 = up[1], u45 = up[2], u67 = up[3];
            acc[0] = ff2(xd, u01.x, acc[0]);
            acc[1] = ff2(xd, u01.y, acc[1]);
            acc[2] = ff2(xd, u23.x, acc[2]);
            acc[3] = ff2(xd, u23.y, acc[3]);
            acc[4] = ff2(xd, u45.x, acc[4]);
            acc[5] = ff2(xd, u45.y, acc[5]);
            acc[6] = ff2(xd, u67.x, acc[6]);
            acc[7] = ff2(xd, u67.y, acc[7]);
        }
    }
#pragma unroll
    for (int p = 0; p < 8; ++p) {
        float lo, hi;
        up2(lo, hi, acc[p]);
        g_scores[((size_t)(b * NH + 2 * p) << 12) + s0 + tid]     = lo * 0.125f;
        g_scores[((size_t)(b * NH + 2 * p + 1) << 12) + s0 + tid] = hi * 0.125f;
    }
}

// ---------------- softmax over s (row = b*NH+h)
__global__ void k_softmax() {
    int row = blockIdx.x;
    float* sc = g_scores + (size_t)row * SS;
    int tid = threadIdx.x;
    float v[16];
    float mx = -1e30f;
#pragma unroll
    for (int i = 0; i < 16; ++i) { v[i] = sc[tid + i * 256]; mx = fmaxf(mx, v[i]); }
    __shared__ float red[256];
    red[tid] = mx; __syncthreads();
    for (int o = 128; o > 0; o >>= 1) { if (tid < o) red[tid] = fmaxf(red[tid], red[tid + o]); __syncthreads(); }
    mx = red[0]; __syncthreads();
    float sum = 0.f;
#pragma unroll
    for (int i = 0; i < 16; ++i) { v[i] = __expf(v[i] - mx); sum += v[i]; }
    red[tid] = sum; __syncthreads();
    for (int o = 128; o > 0; o >>= 1) { if (tid < o) red[tid] += red[tid + o]; __syncthreads(); }
    float inv = 1.f / red[0];
#pragma unroll
    for (int i = 0; i < 16; ++i) sc[tid + i * 256] = v[i] * inv;
}

// ---------------- weighted-sum partials (f32x2, h-pairs): ypart[c][b][h][d]
// grid (16 b, 32 s-chunks of 128), block 128 (4 d per thread)
__global__ void k_wsum(const float* __restrict__ x3) {
    int b = blockIdx.x, c = blockIdx.y;
    int s0 = c * 128;
    __shared__ float at[128][20];  // [s][h pad] rows 80B -> 16B aligned
    int tid = threadIdx.x;
    for (int l = tid; l < NH * 128; l += 128) {
        int h = l >> 7, s = l & 127;
        at[s][h] = g_scores[((size_t)(b * NH + h) << 12) + s0 + s];
    }
    __syncthreads();
    unsigned long long acc[8][4];  // [h-pair][d]
#pragma unroll
    for (int p = 0; p < 8; ++p)
#pragma unroll
        for (int d = 0; d < 4; ++d) acc[p][d] = 0ull;
    int d0 = tid * 4;
    const float* x3b = x3 + ((size_t)b * SS + s0) * DIN + d0;
#pragma unroll 4
    for (int s = 0; s < 128; ++s) {
        float4 xv = *(const float4*)(x3b + (size_t)s * DIN);
        unsigned long long xd[4];
        xd[0] = pk2(xv.x, xv.x); xd[1] = pk2(xv.y, xv.y);
        xd[2] = pk2(xv.z, xv.z); xd[3] = pk2(xv.w, xv.w);
        const ulonglong2* wp = (const ulonglong2*)&at[s][0];
        ulonglong2 wA = wp[0], wB = wp[1], wC = wp[2], wD = wp[3];
        unsigned long long w[8] = {wA.x, wA.y, wB.x, wB.y, wC.x, wC.y, wD.x, wD.y};
#pragma unroll
        for (int p = 0; p < 8; ++p) {
#pragma unroll
            for (int d = 0; d < 4; ++d) acc[p][d] = ff2(xd[d], w[p], acc[p][d]);
        }
    }
    float* yp = g_ypart + ((size_t)(c * BB + b) * NH) * DIN;
#pragma unroll
    for (int p = 0; p < 8; ++p) {
        float lo[4], hi[4];
#pragma unroll
        for (int d = 0; d < 4; ++d) up2(lo[d], hi[d], acc[p][d]);
        *(float4*)(yp + (2 * p) * DIN + d0)     = make_float4(lo[0], lo[1], lo[2], lo[3]);
        *(float4*)(yp + (2 * p + 1) * DIN + d0) = make_float4(hi[0], hi[1], hi[2], hi[3]);
    }
}

// ---------------- av[b, h*64+d] = sum_j ye[b,h,j]*Wv[j, h*64+d] + bv
__global__ void k_av(const float* __restrict__ Wv, const float* __restrict__ bv) {
    int b = blockIdx.x, h = blockIdx.y;
    int d = threadIdx.x & 63, jq = threadIdx.x >> 6;
    __shared__ float yes[DM];
    __shared__ float red[4][64];
    for (int l = threadIdx.x; l < DM; l += 256) yes[l] = g_ye[(size_t)(b * NH + h) * DM + l];
    __syncthreads();
    float acc = 0.f;
    const float* wp = Wv + h * HD + d;
#pragma unroll 8
    for (int j = jq * 256; j < jq * 256 + 256; ++j) acc += yes[j] * wp[(size_t)j * DM];
    red[jq][d] = acc;
    __syncthreads();
    if (jq == 0) {
        float s = red[0][d] + red[1][d] + red[2][d] + red[3][d] + bv[h * HD + d];
        g_av[b * DM + h * HD + d] = s;
    }
}

// ---------------- launch ----------------
extern "C" void kernel_launch(void* const* d_in, const int* in_sizes, int n_in,
                              void* d_out, int out_size) {
    const float* x1  = (const float*)d_in[0];
    const float* x2  = (const float*)d_in[1];
    const float* x3  = (const float*)d_in[2];
    const float* We1 = (const float*)d_in[3];
    const float* be1 = (const float*)d_in[4];
    const float* We2 = (const float*)d_in[5];
    const float* be2 = (const float*)d_in[6];
    const float* Wq  = (const float*)d_in[7];
    const float* bq  = (const float*)d_in[8];
    const float* Wk  = (const float*)d_in[9];
    // d_in[10] = bk: softmax-shift-invariant, exactly dropped
    const float* Wv  = (const float*)d_in[11];
    const float* bv  = (const float*)d_in[12];
    const float* Wo  = (const float*)d_in[13];
    const float* bo  = (const float*)d_in[14];
    float* out = (float*)d_out;

    float *pg_part, *pg_x1e, *pg_q, *pg_t, *pg_ypart, *pg_y, *pg_ye, *pg_av;
    cudaGetSymbolAddress((void**)&pg_part,  g_part);
    cudaGetSymbolAddress((void**)&pg_x1e,   g_x1e);
    cudaGetSymbolAddress((void**)&pg_q,     g_q);
    cudaGetSymbolAddress((void**)&pg_t,     g_t);
    cudaGetSymbolAddress((void**)&pg_ypart, g_ypart);
    cudaGetSymbolAddress((void**)&pg_y,     g_y);
    cudaGetSymbolAddress((void**)&pg_ye,    g_ye);
    cudaGetSymbolAddress((void**)&pg_av,    g_av);

    // 1) x1e = x1 @ We1 + be1
    k_dense16<512><<<64, 256>>>(x1, We1, be1, pg_x1e);
    // 2) q = x1e @ Wq + bq
    k_dense16<1024><<<64, 256>>>(pg_x1e, Wq, bq, pg_q);
    // 3) t[b,h,j] = Wk_h @ q_h
    k_t<<<dim3(NH, 8), 128>>>(Wk);
    // 4) u[b,h,:] = t[b,h,:] @ We2^T  -> transposed g_uT   (512 blocks now)
    k_gemm<256, 512, 1024, 16, true><<<dim3(8, 4, 16), 256>>>(pg_t, We2, pg_part);
    k_reduce_ut<<<512, 256>>>(pg_part);
    // 5) scores + softmax
    k_scores<<<dim3(BB, 32), 128>>>(x2);
    k_softmax<<<BB * NH, 256>>>();
    // 6) y[b,h,:] = attn @ x3
    k_wsum<<<dim3(BB, 32), 128>>>(x3);
    k_reduce<32><<<512, 256>>>(pg_ypart, pg_y, nullptr, 131072, DM);
    // 7) ye = y @ We2 + be2           (512 blocks now)
    k_gemm<256, 1024, 512, 8, false><<<dim3(16, 4, 8), 256>>>(pg_y, We2, pg_part);
    k_reduce<8><<<1024, 256>>>(pg_part, pg_ye, be2, 262144, DM);
    // 8) av = per-head ye @ Wv_h + bv
    k_av<<<dim3(BB, NH), 256>>>(Wv, bv);
    // 9) out = av @ Wo + bo
    k_dense16<1024><<<64, 256>>>(pg_av, Wo, bo, out);
}